// round 1
// baseline (speedup 1.0000x reference)
#include <cuda_runtime.h>
#include <math.h>

typedef unsigned long long u64;

#define BB 32
#define TT 256
#define DD 512
#define VV 32000
#define MR (BB*TT)        // 8192 token rows
#define NSTEP (TT-3)      // 253 scan steps

// ---------------- device scratch (no allocations allowed) ----------------
__device__ float g_Y[MR * 1024];      // ff1 output (relu)
__device__ float g_X[MR * DD];        // pre-LN residual
__device__ float g_h[MR * DD];        // LayerNorm output
__device__ float g_ws[MR];            // h . wg_w + wg_b
__device__ float g_dm[MR];            // h . dem_w + dem_b
__device__ float g_q[BB * DD];        // query vectors
__device__ int   g_memidx[BB * 128];  // token index per memory slot (-1 unused)
__device__ float g_ctxT[DD * BB];     // context, transposed [d][b]

// ---------------- packed fp32x2 helpers ----------------
__device__ __forceinline__ u64 pack_dup(float x) {
    u64 r; asm("mov.b64 %0, {%1, %1};" : "=l"(r) : "f"(x)); return r;
}
__device__ __forceinline__ u64 ffma2(u64 a, u64 b, u64 c) {
    u64 d; asm("fma.rn.f32x2 %0, %1, %2, %3;" : "=l"(d) : "l"(a), "l"(b), "l"(c)); return d;
}
__device__ __forceinline__ void unpack2(u64 v, float& lo, float& hi) {
    asm("mov.b64 {%0, %1}, %2;" : "=f"(lo), "=f"(hi) : "l"(v));
}

// ---------------- generic fp32 GEMM body (BM=128,BN=128,BK=16, 256 thr, 8x8/thr) ----------------
template<bool GATHER, bool RELU, bool RESID, int N, int K>
__device__ __forceinline__ void gemm_body(
    const float* __restrict__ A, const float* __restrict__ W,
    const float* __restrict__ bias, float* __restrict__ C,
    const int* __restrict__ seq, const float* __restrict__ embed)
{
    constexpr int BM = 128, BN = 128, BK = 16;
    __shared__ __align__(16) float As[BK][BM];
    __shared__ __align__(16) float Bs[BK][BN];

    const int tid = threadIdx.x;
    const int m0 = blockIdx.y * BM;
    const int n0 = blockIdx.x * BN;
    const int tm = tid >> 4;     // 0..15
    const int tn = tid & 15;     // 0..15

    u64 acc[8][4];
#pragma unroll
    for (int i = 0; i < 8; i++)
#pragma unroll
        for (int j = 0; j < 4; j++) acc[i][j] = 0ull;

    for (int k0 = 0; k0 < K; k0 += BK) {
        // load A tile (BM x BK), store transposed As[k][m]
#pragma unroll
        for (int f = tid; f < BM * BK / 4; f += 256) {
            int r  = f >> 2;            // row within tile (BK/4 = 4 float4 per row)
            int kc = (f & 3) << 2;
            const float* src;
            if (GATHER) src = embed + (size_t)seq[m0 + r] * DD + k0 + kc;
            else        src = A + (size_t)(m0 + r) * K + k0 + kc;
            float4 v = *(const float4*)src;
            As[kc + 0][r] = v.x; As[kc + 1][r] = v.y;
            As[kc + 2][r] = v.z; As[kc + 3][r] = v.w;
        }
        // load B tile (BK x BN)
#pragma unroll
        for (int f = tid; f < BK * BN / 4; f += 256) {
            int r = f >> 5;             // BN/4 = 32 float4 per row
            int c = (f & 31) << 2;
            *(float4*)&Bs[r][c] = *(const float4*)(W + (size_t)(k0 + r) * N + n0 + c);
        }
        __syncthreads();
#pragma unroll
        for (int k = 0; k < BK; k++) {
            float4 a0 = *(const float4*)&As[k][tm * 8];
            float4 a1 = *(const float4*)&As[k][tm * 8 + 4];
            ulonglong2 p0 = *(const ulonglong2*)&Bs[k][tn * 8];
            ulonglong2 p1 = *(const ulonglong2*)&Bs[k][tn * 8 + 4];
            u64 b0 = p0.x, b1 = p0.y, b2 = p1.x, b3 = p1.y;
            float av[8] = {a0.x, a0.y, a0.z, a0.w, a1.x, a1.y, a1.z, a1.w};
#pragma unroll
            for (int m = 0; m < 8; m++) {
                u64 am = pack_dup(av[m]);
                acc[m][0] = ffma2(am, b0, acc[m][0]);
                acc[m][1] = ffma2(am, b1, acc[m][1]);
                acc[m][2] = ffma2(am, b2, acc[m][2]);
                acc[m][3] = ffma2(am, b3, acc[m][3]);
            }
        }
        __syncthreads();
    }
    // epilogue
#pragma unroll
    for (int m = 0; m < 8; m++) {
        int row = m0 + tm * 8 + m;
        const float* emrow = RESID ? (embed + (size_t)seq[row] * DD) : (const float*)0;
#pragma unroll
        for (int j = 0; j < 4; j++) {
            int n = n0 + tn * 8 + j * 2;
            float lo, hi;
            unpack2(acc[m][j], lo, hi);
            lo += bias[n]; hi += bias[n + 1];
            if (RELU) { lo = fmaxf(lo, 0.f); hi = fmaxf(hi, 0.f); }
            if (RESID) { lo += emrow[n]; hi += emrow[n + 1]; }
            float2 o; o.x = lo; o.y = hi;
            *(float2*)&C[(size_t)row * N + n] = o;
        }
    }
}

__global__ void __launch_bounds__(256, 2) gemm1_kernel(
    const int* __restrict__ seq, const float* __restrict__ embed,
    const float* __restrict__ w, const float* __restrict__ bias)
{
    gemm_body<true, true, false, 1024, 512>(nullptr, w, bias, g_Y, seq, embed);
}
__global__ void __launch_bounds__(256, 2) gemm2_kernel(
    const int* __restrict__ seq, const float* __restrict__ embed,
    const float* __restrict__ w, const float* __restrict__ bias)
{
    gemm_body<false, false, true, 512, 1024>(g_Y, w, bias, g_X, seq, embed);
}

// ---------------- LayerNorm + per-token gate/demote scalars ----------------
__device__ __forceinline__ float blk_reduce_256(float v, float* red) {
    int tid = threadIdx.x;
#pragma unroll
    for (int o = 16; o; o >>= 1) v += __shfl_xor_sync(0xffffffffu, v, o);
    __syncthreads();
    if ((tid & 31) == 0) red[tid >> 5] = v;
    __syncthreads();
    float s = 0.f;
#pragma unroll
    for (int i = 0; i < 8; i++) s += red[i];
    return s;
}

__global__ void __launch_bounds__(256) ln_kernel(
    const float* __restrict__ lng, const float* __restrict__ lnb,
    const float* __restrict__ wgw, const float* __restrict__ wgb,
    const float* __restrict__ demw, const float* __restrict__ demb)
{
    int row = blockIdx.x, tid = threadIdx.x;
    __shared__ float red[8];
    const float* xr = g_X + (size_t)row * DD;
    float v0 = xr[tid], v1 = xr[tid + 256];

    float total = blk_reduce_256(v0 + v1, red);
    float mu = total * (1.f / 512.f);
    float d0 = v0 - mu, d1 = v1 - mu;
    float ssq = blk_reduce_256(d0 * d0 + d1 * d1, red);
    float var = ssq * (1.f / 512.f);
    float rstd = 1.f / sqrtf(var + 1e-5f);
    float h0 = d0 * rstd * lng[tid] + lnb[tid];
    float h1 = d1 * rstd * lng[tid + 256] + lnb[tid + 256];
    g_h[(size_t)row * DD + tid] = h0;
    g_h[(size_t)row * DD + tid + 256] = h1;

    float wsp = blk_reduce_256(h0 * wgw[tid] + h1 * wgw[tid + 256], red);
    float dmp = blk_reduce_256(h0 * demw[tid] + h1 * demw[tid + 256], red);
    if (tid == 0) {
        g_ws[row] = wsp + wgb[0];
        g_dm[row] = dmp + demb[0];
    }
}

// ---------------- q = h[:, -1] @ q_w + q_b ----------------
__global__ void __launch_bounds__(512) q_kernel(
    const float* __restrict__ qw, const float* __restrict__ qb)
{
    int b = blockIdx.x, tid = threadIdx.x;
    __shared__ float hs[512];
    hs[tid] = g_h[(size_t)(b * TT + TT - 1) * DD + tid];
    __syncthreads();
    float acc = 0.f;
#pragma unroll 8
    for (int k = 0; k < 512; k++) acc += hs[k] * qw[k * 512 + tid];
    g_q[b * DD + tid] = acc + qb[tid];
}

// ---------------- tiered memory scan: pure index tracking, 1 warp per batch ----------------
__global__ void __launch_bounds__(32) scan_kernel()
{
    int b = blockIdx.x, l = threadIdx.x;
    __shared__ float wss[256], dss[256];
    for (int t = l; t < NSTEP; t += 32) {
        wss[t] = g_ws[b * TT + t];
        dss[t] = g_dm[b * TT + t];
    }
    __syncthreads();

    int  ftok = -1;  bool fu = false;               // fast slot l
    int  st0 = -1, st1 = -1, st2 = -1;              // slow slots l, 32+l, 64+l
    int  sa0 = 0, sa1 = 0, sa2 = 0;
    bool su0 = false, su1 = false, su2 = false;

    for (int t = 0; t < NSTEP; t++) {
        float ws = 1.f / (1.f + expf(-wss[t]));
        bool write = (ws >= 0.4f);
        sa0 += su0; sa1 += su1; sa2 += su2;         // ages increment regardless
        if (!write) continue;                        // warp-uniform

        unsigned freeb = __ballot_sync(0xffffffffu, !fu);
        int target;
        if (freeb) {
            target = __ffs(freeb) - 1;               // first free fast slot
        } else {
            // demote path: argmin over ds (first occurrence)
            float bv = dss[ftok]; int bi = l;
#pragma unroll
            for (int o = 16; o; o >>= 1) {
                float ov = __shfl_xor_sync(0xffffffffu, bv, o);
                int   oi = __shfl_xor_sync(0xffffffffu, bi, o);
                if (ov < bv || (ov == bv && oi < bi)) { bv = ov; bi = oi; }
            }
            target = bi;
            int dtok = __shfl_sync(0xffffffffu, ftok, target);

            unsigned f0 = __ballot_sync(0xffffffffu, !su0);
            unsigned f1 = __ballot_sync(0xffffffffu, !su1);
            unsigned f2 = __ballot_sync(0xffffffffu, !su2);
            int ss;
            if (f0)      ss = __ffs(f0) - 1;
            else if (f1) ss = 32 + __ffs(f1) - 1;
            else if (f2) ss = 64 + __ffs(f2) - 1;
            else {
                int mv = sa0, mi = l;                // argmax sa, first occurrence
                if (sa1 > mv) { mv = sa1; mi = 32 + l; }
                if (sa2 > mv) { mv = sa2; mi = 64 + l; }
#pragma unroll
                for (int o = 16; o; o >>= 1) {
                    int ov = __shfl_xor_sync(0xffffffffu, mv, o);
                    int oi = __shfl_xor_sync(0xffffffffu, mi, o);
                    if (ov > mv || (ov == mv && oi < mi)) { mv = ov; mi = oi; }
                }
                ss = mi;
            }
            int g = ss >> 5, ol = ss & 31;
            if (l == ol) {
                if (g == 0)      { st0 = dtok; sa0 = 0; su0 = true; }
                else if (g == 1) { st1 = dtok; sa1 = 0; su1 = true; }
                else             { st2 = dtok; sa2 = 0; su2 = true; }
            }
        }
        if (l == target) { ftok = t; fu = true; }
    }

    g_memidx[b * 128 + l]      = fu  ? ftok : -1;
    g_memidx[b * 128 + 32 + l] = su0 ? st0  : -1;
    g_memidx[b * 128 + 64 + l] = su1 ? st1  : -1;
    g_memidx[b * 128 + 96 + l] = su2 ? st2  : -1;
}

// ---------------- read head: scores, masked softmax, ctx ----------------
__device__ __forceinline__ float blk128_max(float v, float* red) {
    int tid = threadIdx.x;
#pragma unroll
    for (int o = 16; o; o >>= 1) v = fmaxf(v, __shfl_xor_sync(0xffffffffu, v, o));
    __syncthreads();
    if ((tid & 31) == 0) red[tid >> 5] = v;
    __syncthreads();
    return fmaxf(fmaxf(red[0], red[1]), fmaxf(red[2], red[3]));
}
__device__ __forceinline__ float blk128_sum(float v, float* red) {
    int tid = threadIdx.x;
#pragma unroll
    for (int o = 16; o; o >>= 1) v += __shfl_xor_sync(0xffffffffu, v, o);
    __syncthreads();
    if ((tid & 31) == 0) red[tid >> 5] = v;
    __syncthreads();
    return red[0] + red[1] + red[2] + red[3];
}

__global__ void __launch_bounds__(128) readhead_kernel()
{
    int b = blockIdx.x, tid = threadIdx.x;
    __shared__ float qs[512];
    __shared__ float attn[128];
    __shared__ int   idx[128];
    __shared__ float red[4];

    for (int i = tid; i < 512; i += 128) qs[i] = g_q[b * DD + i];
    int tok = g_memidx[b * 128 + tid];
    idx[tid] = tok;
    __syncthreads();

    float s = -1e9f;
    if (tok >= 0) {
        const float* m = g_h + (size_t)(b * TT + tok) * DD;
        float acc = 0.f;
#pragma unroll 8
        for (int k = 0; k < 512; k++) acc += m[k] * qs[k];
        s = acc;
    }
    float mx = blk128_max(s, red);
    __syncthreads();
    float e = expf(s - mx);
    float denom = blk128_sum(e, red);
    attn[tid] = e / denom;
    __syncthreads();

    for (int d = tid; d < 512; d += 128) {
        float acc = 0.f;
        for (int n = 0; n < 128; n++) {
            int tk = idx[n];
            if (tk >= 0) acc += attn[n] * g_h[(size_t)(b * TT + tk) * DD + d];
        }
        g_ctxT[d * BB + b] = acc;
    }
}

// ---------------- logits = ctx @ out_w + out_b ----------------
__global__ void __launch_bounds__(256) out_kernel(
    const float* __restrict__ outw, const float* __restrict__ outb,
    float* __restrict__ out)
{
    __shared__ __align__(16) float cst[256 * 32];   // [d_local][b]
    int v = blockIdx.x * 256 + threadIdx.x;
    u64 acc[16];
#pragma unroll
    for (int j = 0; j < 16; j++) acc[j] = 0ull;

    for (int d0 = 0; d0 < 512; d0 += 256) {
        __syncthreads();
        for (int i = threadIdx.x; i < 256 * 32; i += 256)
            cst[i] = g_ctxT[d0 * 32 + i];
        __syncthreads();
#pragma unroll 4
        for (int dl = 0; dl < 256; dl++) {
            float w = outw[(size_t)(d0 + dl) * VV + v];
            u64 w2 = pack_dup(w);
            const ulonglong2* cp = (const ulonglong2*)&cst[dl * 32];
#pragma unroll
            for (int j = 0; j < 8; j++) {
                ulonglong2 p = cp[j];
                acc[2 * j]     = ffma2(w2, p.x, acc[2 * j]);
                acc[2 * j + 1] = ffma2(w2, p.y, acc[2 * j + 1]);
            }
        }
    }
    float ob = outb[v];
#pragma unroll
    for (int j = 0; j < 16; j++) {
        float lo, hi;
        unpack2(acc[j], lo, hi);
        out[(size_t)(2 * j) * VV + v]     = lo + ob;
        out[(size_t)(2 * j + 1) * VV + v] = hi + ob;
    }
}

// ---------------- launch ----------------
extern "C" void kernel_launch(void* const* d_in, const int* in_sizes, int n_in,
                              void* d_out, int out_size)
{
    const int*   seq   = (const int*)d_in[0];
    const float* embed = (const float*)d_in[1];
    const float* ff1w  = (const float*)d_in[2];
    const float* ff1b  = (const float*)d_in[3];
    const float* ff2w  = (const float*)d_in[4];
    const float* ff2b  = (const float*)d_in[5];
    const float* lng   = (const float*)d_in[6];
    const float* lnb   = (const float*)d_in[7];
    const float* wgw   = (const float*)d_in[8];
    const float* wgb   = (const float*)d_in[9];
    const float* demw  = (const float*)d_in[10];
    const float* demb  = (const float*)d_in[11];
    const float* qw    = (const float*)d_in[12];
    const float* qb    = (const float*)d_in[13];
    const float* outw  = (const float*)d_in[14];
    const float* outb  = (const float*)d_in[15];
    float* out = (float*)d_out;

    gemm1_kernel<<<dim3(1024 / 128, MR / 128), 256>>>(seq, embed, ff1w, ff1b);
    gemm2_kernel<<<dim3(512 / 128, MR / 128), 256>>>(seq, embed, ff2w, ff2b);
    ln_kernel<<<MR, 256>>>(lng, lnb, wgw, wgb, demw, demb);
    q_kernel<<<BB, 512>>>(qw, qb);
    scan_kernel<<<BB, 32>>>();
    readhead_kernel<<<BB, 128>>>();
    out_kernel<<<VV / 256, 256>>>(outw, outb, out);
}

// round 3
// speedup vs baseline: 1.2548x; 1.2548x over previous
#include <cuda_runtime.h>
#include <math.h>
#include <stdint.h>

typedef unsigned long long u64;

#define BB 32
#define TT 256
#define DD 512
#define VV 32000
#define MR (BB*TT)        // 8192 token rows
#define NSTEP (TT-3)      // 253 scan steps

// ======================= device scratch (fragment-ordered operands) =======================
// A-fragment layout (for mma m16n8k8, A row-major m16k8):
//   float4 slot index = (tile_m * (K/8) + tile_k) * 32 + lane
//   components q0..q3 = A[tm*16 + (lane>>2) + 8*(q&1)][tk*8 + (lane&3) + 4*(q>>1)]
// B-fragment layout (B col-major k8n8):
//   float2 slot index = (tile_n * (K/8) + tile_k) * 32 + lane
//   components q0,q1  = W[tk*8 + (lane&3) + 4*q][tn*8 + (lane>>2)]   (original w[k][n])
__device__ __align__(256) float gAhi[MR * DD];
__device__ __align__(256) float gAlo[MR * DD];
__device__ __align__(256) float gYhi[MR * 1024];
__device__ __align__(256) float gYlo[MR * 1024];
__device__ __align__(256) float gW1hi[1024 * 512];
__device__ __align__(256) float gW1lo[1024 * 512];
__device__ __align__(256) float gW2hi[512 * 1024];
__device__ __align__(256) float gW2lo[512 * 1024];
__device__ float g_X[MR * DD];        // pre-LN residual (fp32)
__device__ float g_h[MR * DD];        // LayerNorm output
__device__ float g_ws[MR];
__device__ float g_dm[MR];
__device__ float g_q[BB * DD];
__device__ int   g_memidx[BB * 128];
__device__ float g_ctxT[DD * BB];

// ======================= helpers =======================
__device__ __forceinline__ float to_tf32(float x) {
    float r; asm("cvt.rna.tf32.f32 %0, %1;" : "=f"(r) : "f"(x)); return r;
}
__device__ __forceinline__ void split2(float v, float& hi, float& lo) {
    hi = to_tf32(v);
    lo = to_tf32(v - hi);
}
__device__ __forceinline__ uint32_t smem_u32(const void* p) {
    uint32_t a;
    asm("{ .reg .u64 t; cvta.to.shared.u64 t, %1; cvt.u32.u64 %0, t; }" : "=r"(a) : "l"(p));
    return a;
}
__device__ __forceinline__ void cp16(uint32_t dst, const void* src) {
    asm volatile("cp.async.cg.shared.global [%0], [%1], 16;" :: "r"(dst), "l"(src));
}
#define CP_COMMIT() asm volatile("cp.async.commit_group;" ::: "memory")
#define CP_WAIT(n)  asm volatile("cp.async.wait_group %0;" :: "n"(n) : "memory")

__device__ __forceinline__ void mma8(float* c, uint4 a, uint2 b) {
    asm volatile(
        "mma.sync.aligned.m16n8k8.row.col.f32.tf32.tf32.f32 "
        "{%0,%1,%2,%3}, {%4,%5,%6,%7}, {%8,%9}, {%0,%1,%2,%3};"
        : "+f"(c[0]), "+f"(c[1]), "+f"(c[2]), "+f"(c[3])
        : "r"(a.x), "r"(a.y), "r"(a.z), "r"(a.w), "r"(b.x), "r"(b.y));
}

// packed fp32x2 (for out_kernel)
__device__ __forceinline__ u64 pack_dup(float x) {
    u64 r; asm("mov.b64 %0, {%1, %1};" : "=l"(r) : "f"(x)); return r;
}
__device__ __forceinline__ u64 ffma2(u64 a, u64 b, u64 c) {
    u64 d; asm("fma.rn.f32x2 %0, %1, %2, %3;" : "=l"(d) : "l"(a), "l"(b), "l"(c)); return d;
}
__device__ __forceinline__ void unpack2(u64 v, float& lo, float& hi) {
    asm("mov.b64 {%0, %1}, %2;" : "=f"(lo), "=f"(hi) : "l"(v));
}

// ======================= prep: tokens -> A fragments =======================
__global__ void __launch_bounds__(256) prep_tok_frag(
    const int* __restrict__ seq, const float* __restrict__ embed)
{
    int slot = blockIdx.x * 256 + threadIdx.x;      // < 512*64*32
    int lane = slot & 31;
    int tk = (slot >> 5) & 63;
    int tm = slot >> 11;
    int r = lane >> 2, c = lane & 3;
    int m0 = tm * 16 + r;
    int kb = tk * 8 + c;
    int s0 = seq[m0], s1 = seq[m0 + 8];
    float v0 = embed[(size_t)s0 * DD + kb];
    float v1 = embed[(size_t)s1 * DD + kb];
    float v2 = embed[(size_t)s0 * DD + kb + 4];
    float v3 = embed[(size_t)s1 * DD + kb + 4];
    float4 h, l;
    split2(v0, h.x, l.x); split2(v1, h.y, l.y);
    split2(v2, h.z, l.z); split2(v3, h.w, l.w);
    ((float4*)gAhi)[slot] = h;
    ((float4*)gAlo)[slot] = l;
}

// ======================= prep: weights -> B fragments =======================
__global__ void __launch_bounds__(256) prep_w_frag(
    const float* __restrict__ W, int K8, int N,
    float* __restrict__ Bhi, float* __restrict__ Blo)
{
    int slot = blockIdx.x * 256 + threadIdx.x;      // (N/8)*(K/8)*32
    int lane = slot & 31;
    int tkn = slot >> 5;
    int tk = tkn % K8;
    int tn = tkn / K8;
    int k = tk * 8 + (lane & 3);
    int n = tn * 8 + (lane >> 2);
    float v0 = W[(size_t)k * N + n];
    float v1 = W[(size_t)(k + 4) * N + n];
    float2 h, l;
    split2(v0, h.x, l.x); split2(v1, h.y, l.y);
    ((float2*)Bhi)[slot] = h;
    ((float2*)Blo)[slot] = l;
}

// ======================= 3xTF32 mma GEMM =======================
// tile 128x128, BK=32, 256 threads (8 warps as 4m x 2n, each 32x64)
#define OFF_AH 0
#define OFF_AL 16384
#define OFF_BH 32768
#define OFF_BL 49152
#define STAGE  65536
#define SMEM_REQ (2 * STAGE)
#define CS_STRIDE 132

template<int KDIM, bool G1>
__global__ void __launch_bounds__(256, 1) mma_gemm(
    const float* __restrict__ Ahi, const float* __restrict__ Alo,
    const float* __restrict__ Bhi, const float* __restrict__ Blo,
    const float* __restrict__ bias,
    const int* __restrict__ seq, const float* __restrict__ embed)
{
    extern __shared__ char smch[];
    const uint32_t smb = smem_u32(smch);
    const int tid = threadIdx.x;
    const int wid = tid >> 5;
    const int lane = tid & 31;
    const int warp_m = wid & 3;       // 0..3 -> 32 rows each
    const int warp_n = wid >> 2;      // 0..1 -> 64 cols each
    const int m0 = blockIdx.y * 128;
    const int n0 = blockIdx.x * 128;
    const int tm0 = m0 >> 4;          // base tile_m
    const int tn0 = n0 >> 3;          // base tile_n
    constexpr int AK8 = KDIM / 8;
    constexpr int NCH = KDIM / 32;

    float acc[2][8][4];
#pragma unroll
    for (int mt = 0; mt < 2; mt++)
#pragma unroll
        for (int nt = 0; nt < 8; nt++)
#pragma unroll
            for (int j = 0; j < 4; j++) acc[mt][nt][j] = 0.f;

    // ---- async copy of one chunk into a stage ----
    auto issue = [&](int ch) {
        int stage = ch & 1;
        uint32_t sb = smb + stage * STAGE;
        int tk0 = ch * 4;
#pragma unroll
        for (int it = 0; it < 4; it++) {
            int f = it * 256 + tid;
            int tm_l = f >> 7, tk_l = (f >> 5) & 3, ln = f & 31;
            size_t g4 = ((size_t)(tm0 + tm_l) * AK8 + tk0 + tk_l) * 32 + ln;
            cp16(sb + OFF_AH + f * 16, Ahi + g4 * 4);
            cp16(sb + OFF_AL + f * 16, Alo + g4 * 4);
        }
#pragma unroll
        for (int it = 0; it < 4; it++) {
            int f = it * 256 + tid;
            int tn_l = f >> 6, tk_l = (f >> 4) & 3, lp = f & 15;
            size_t g4 = ((size_t)(tn0 + tn_l) * AK8 + tk0 + tk_l) * 16 + lp;
            cp16(sb + OFF_BH + f * 16, Bhi + g4 * 4);
            cp16(sb + OFF_BL + f * 16, Blo + g4 * 4);
        }
    };

    issue(0); CP_COMMIT();

    const int wm2 = warp_m * 2;
    const int wn8 = warp_n * 8;

    for (int i = 0; i < NCH; i++) {
        if (i + 1 < NCH) { issue(i + 1); CP_COMMIT(); CP_WAIT(1); }
        else             { CP_WAIT(0); }
        __syncthreads();
        int stage = i & 1;
        const char* sbase = smch + stage * STAGE;
        const uint4* Ah4 = (const uint4*)(sbase + OFF_AH);
        const uint4* Al4 = (const uint4*)(sbase + OFF_AL);
        const uint2* Bh2 = (const uint2*)(sbase + OFF_BH);
        const uint2* Bl2 = (const uint2*)(sbase + OFF_BL);
#pragma unroll
        for (int kk = 0; kk < 4; kk++) {
            uint4 ah[2], al[2];
#pragma unroll
            for (int mt = 0; mt < 2; mt++) {
                int idx = ((wm2 + mt) * 4 + kk) * 32 + lane;
                ah[mt] = Ah4[idx];
                al[mt] = Al4[idx];
            }
            uint2 bh[8], bl[8];
#pragma unroll
            for (int nt = 0; nt < 8; nt++) {
                int idx = ((wn8 + nt) * 4 + kk) * 32 + lane;
                bh[nt] = Bh2[idx];
                bl[nt] = Bl2[idx];
            }
#pragma unroll
            for (int mt = 0; mt < 2; mt++)
#pragma unroll
                for (int nt = 0; nt < 8; nt++) {
                    mma8(acc[mt][nt], ah[mt], bh[nt]);
                    mma8(acc[mt][nt], ah[mt], bl[nt]);
                    mma8(acc[mt][nt], al[mt], bh[nt]);
                }
        }
        __syncthreads();
    }

    // ---- epilogue: stage C tile in smem (128 x 128, stride 132) ----
    float* Cs = (float*)smch;
    {
        int r0 = warp_m * 32 + (lane >> 2);
        int cb = warp_n * 64 + 2 * (lane & 3);
#pragma unroll
        for (int mt = 0; mt < 2; mt++)
#pragma unroll
            for (int nt = 0; nt < 8; nt++) {
                int row = r0 + mt * 16;
                int col = cb + nt * 8;
                Cs[row * CS_STRIDE + col]           = acc[mt][nt][0];
                Cs[row * CS_STRIDE + col + 1]       = acc[mt][nt][1];
                Cs[(row + 8) * CS_STRIDE + col]     = acc[mt][nt][2];
                Cs[(row + 8) * CS_STRIDE + col + 1] = acc[mt][nt][3];
            }
    }
    __syncthreads();

    if (G1) {
        // write relu(C+bias) as A-fragments for gemm2 (K2 = 1024 -> YK8 = 128)
        for (int t = wid; t < 128; t += 8) {
            int tm = t >> 4, tkl = t & 15;
            float4 h4, l4;
            float* hp = &h4.x; float* lp = &l4.x;
#pragma unroll
            for (int q = 0; q < 4; q++) {
                int row = tm * 16 + (lane >> 2) + (q & 1) * 8;
                int col = tkl * 8 + (lane & 3) + (q >> 1) * 4;
                float v = Cs[row * CS_STRIDE + col] + bias[n0 + col];
                v = fmaxf(v, 0.f);
                split2(v, hp[q], lp[q]);
            }
            size_t slot = ((size_t)(tm0 + tm) * 128 + (n0 >> 3) + tkl) * 32 + lane;
            ((float4*)gYhi)[slot] = h4;
            ((float4*)gYlo)[slot] = l4;
        }
    } else {
        // write X = C + bias + embed residual (linear fp32)
#pragma unroll
        for (int it = 0; it < 16; it++) {
            int f = it * 256 + tid;
            int row = f >> 5;
            int c4 = (f & 31) * 4;
            float4 v = *(float4*)(Cs + row * CS_STRIDE + c4);
            int grow = m0 + row;
            int gcol = n0 + c4;
            float4 e = *(const float4*)(embed + (size_t)seq[grow] * DD + gcol);
            v.x += bias[gcol] + e.x;
            v.y += bias[gcol + 1] + e.y;
            v.z += bias[gcol + 2] + e.z;
            v.w += bias[gcol + 3] + e.w;
            *(float4*)(g_X + (size_t)grow * DD + gcol) = v;
        }
    }
}

// ======================= LayerNorm + gate scalars =======================
__device__ __forceinline__ float blk_reduce_256(float v, float* red) {
    int tid = threadIdx.x;
#pragma unroll
    for (int o = 16; o; o >>= 1) v += __shfl_xor_sync(0xffffffffu, v, o);
    __syncthreads();
    if ((tid & 31) == 0) red[tid >> 5] = v;
    __syncthreads();
    float s = 0.f;
#pragma unroll
    for (int i = 0; i < 8; i++) s += red[i];
    return s;
}

__global__ void __launch_bounds__(256) ln_kernel(
    const float* __restrict__ lng, const float* __restrict__ lnb,
    const float* __restrict__ wgw, const float* __restrict__ wgb,
    const float* __restrict__ demw, const float* __restrict__ demb)
{
    int row = blockIdx.x, tid = threadIdx.x;
    __shared__ float red[8];
    const float* xr = g_X + (size_t)row * DD;
    float v0 = xr[tid], v1 = xr[tid + 256];

    float total = blk_reduce_256(v0 + v1, red);
    float mu = total * (1.f / 512.f);
    float d0 = v0 - mu, d1 = v1 - mu;
    float ssq = blk_reduce_256(d0 * d0 + d1 * d1, red);
    float var = ssq * (1.f / 512.f);
    float rstd = 1.f / sqrtf(var + 1e-5f);
    float h0 = d0 * rstd * lng[tid] + lnb[tid];
    float h1 = d1 * rstd * lng[tid + 256] + lnb[tid + 256];
    g_h[(size_t)row * DD + tid] = h0;
    g_h[(size_t)row * DD + tid + 256] = h1;

    float wsp = blk_reduce_256(h0 * wgw[tid] + h1 * wgw[tid + 256], red);
    float dmp = blk_reduce_256(h0 * demw[tid] + h1 * demw[tid + 256], red);
    if (tid == 0) {
        g_ws[row] = wsp + wgb[0];
        g_dm[row] = dmp + demb[0];
    }
}

// ======================= q = h[:, -1] @ q_w + q_b =======================
__global__ void __launch_bounds__(128) q_kernel(
    const float* __restrict__ qw, const float* __restrict__ qb)
{
    int b = blockIdx.y, tid = threadIdx.x;
    int n = blockIdx.x * 128 + tid;
    __shared__ float hs[512];
    *(float4*)(hs + tid * 4) = *(const float4*)(g_h + (size_t)(b * TT + TT - 1) * DD + tid * 4);
    __syncthreads();
    float acc = 0.f;
#pragma unroll 8
    for (int k = 0; k < 512; k++) acc += hs[k] * qw[(size_t)k * 512 + n];
    g_q[b * DD + n] = acc + qb[n];
}

// ======================= tiered memory scan =======================
__global__ void __launch_bounds__(32) scan_kernel()
{
    int b = blockIdx.x, l = threadIdx.x;
    __shared__ float wss[256], dss[256];
    for (int t = l; t < NSTEP; t += 32) {
        wss[t] = g_ws[b * TT + t];
        dss[t] = g_dm[b * TT + t];
    }
    __syncthreads();

    int  ftok = -1;  bool fu = false;
    int  st0 = -1, st1 = -1, st2 = -1;
    int  sa0 = 0, sa1 = 0, sa2 = 0;
    bool su0 = false, su1 = false, su2 = false;

    for (int t = 0; t < NSTEP; t++) {
        float ws = 1.f / (1.f + expf(-wss[t]));
        bool write = (ws >= 0.4f);
        sa0 += su0; sa1 += su1; sa2 += su2;
        if (!write) continue;

        unsigned freeb = __ballot_sync(0xffffffffu, !fu);
        int target;
        if (freeb) {
            target = __ffs(freeb) - 1;
        } else {
            float bv = dss[ftok]; int bi = l;
#pragma unroll
            for (int o = 16; o; o >>= 1) {
                float ov = __shfl_xor_sync(0xffffffffu, bv, o);
                int   oi = __shfl_xor_sync(0xffffffffu, bi, o);
                if (ov < bv || (ov == bv && oi < bi)) { bv = ov; bi = oi; }
            }
            target = bi;
            int dtok = __shfl_sync(0xffffffffu, ftok, target);

            unsigned f0 = __ballot_sync(0xffffffffu, !su0);
            unsigned f1 = __ballot_sync(0xffffffffu, !su1);
            unsigned f2 = __ballot_sync(0xffffffffu, !su2);
            int ss;
            if (f0)      ss = __ffs(f0) - 1;
            else if (f1) ss = 32 + __ffs(f1) - 1;
            else if (f2) ss = 64 + __ffs(f2) - 1;
            else {
                int mv = sa0, mi = l;
                if (sa1 > mv) { mv = sa1; mi = 32 + l; }
                if (sa2 > mv) { mv = sa2; mi = 64 + l; }
#pragma unroll
                for (int o = 16; o; o >>= 1) {
                    int ov = __shfl_xor_sync(0xffffffffu, mv, o);
                    int oi = __shfl_xor_sync(0xffffffffu, mi, o);
                    if (ov > mv || (ov == mv && oi < mi)) { mv = ov; mi = oi; }
                }
                ss = mi;
            }
            int g = ss >> 5, ol = ss & 31;
            if (l == ol) {
                if (g == 0)      { st0 = dtok; sa0 = 0; su0 = true; }
                else if (g == 1) { st1 = dtok; sa1 = 0; su1 = true; }
                else             { st2 = dtok; sa2 = 0; su2 = true; }
            }
        }
        if (l == target) { ftok = t; fu = true; }
    }

    g_memidx[b * 128 + l]      = fu  ? ftok : -1;
    g_memidx[b * 128 + 32 + l] = su0 ? st0  : -1;
    g_memidx[b * 128 + 64 + l] = su1 ? st1  : -1;
    g_memidx[b * 128 + 96 + l] = su2 ? st2  : -1;
}

// ======================= read head =======================
__device__ __forceinline__ float blk128_max(float v, float* red) {
    int tid = threadIdx.x;
#pragma unroll
    for (int o = 16; o; o >>= 1) v = fmaxf(v, __shfl_xor_sync(0xffffffffu, v, o));
    __syncthreads();
    if ((tid & 31) == 0) red[tid >> 5] = v;
    __syncthreads();
    return fmaxf(fmaxf(red[0], red[1]), fmaxf(red[2], red[3]));
}
__device__ __forceinline__ float blk128_sum(float v, float* red) {
    int tid = threadIdx.x;
#pragma unroll
    for (int o = 16; o; o >>= 1) v += __shfl_xor_sync(0xffffffffu, v, o);
    __syncthreads();
    if ((tid & 31) == 0) red[tid >> 5] = v;
    __syncthreads();
    return red[0] + red[1] + red[2] + red[3];
}

__global__ void __launch_bounds__(128) readhead_kernel()
{
    int b = blockIdx.x, tid = threadIdx.x;
    __shared__ float qs[512];
    __shared__ float attn[128];
    __shared__ int   idx[128];
    __shared__ float red[4];

    for (int i = tid; i < 512; i += 128) qs[i] = g_q[b * DD + i];
    int tok = g_memidx[b * 128 + tid];
    idx[tid] = tok;
    __syncthreads();

    float s = -1e9f;
    if (tok >= 0) {
        const float* m = g_h + (size_t)(b * TT + tok) * DD;
        float acc = 0.f;
#pragma unroll 8
        for (int k = 0; k < 512; k++) acc += m[k] * qs[k];
        s = acc;
    }
    float mx = blk128_max(s, red);
    __syncthreads();
    float e = expf(s - mx);
    float denom = blk128_sum(e, red);
    attn[tid] = e / denom;
    __syncthreads();

    for (int d = tid; d < 512; d += 128) {
        float acc = 0.f;
        for (int n = 0; n < 128; n++) {
            int tk = idx[n];
            if (tk >= 0) acc += attn[n] * g_h[(size_t)(b * TT + tk) * DD + d];
        }
        g_ctxT[d * BB + b] = acc;
    }
}

// ======================= logits = ctx @ out_w + out_b =======================
__global__ void __launch_bounds__(256) out_kernel(
    const float* __restrict__ outw, const float* __restrict__ outb,
    float* __restrict__ out)
{
    __shared__ __align__(16) float cst[256 * 32];
    int v = blockIdx.x * 256 + threadIdx.x;
    u64 acc[16];
#pragma unroll
    for (int j = 0; j < 16; j++) acc[j] = 0ull;

    for (int d0 = 0; d0 < 512; d0 += 256) {
        __syncthreads();
        for (int i = threadIdx.x; i < 256 * 32; i += 256)
            cst[i] = g_ctxT[d0 * 32 + i];
        __syncthreads();
#pragma unroll 4
        for (int dl = 0; dl < 256; dl++) {
            float w = outw[(size_t)(d0 + dl) * VV + v];
            u64 w2 = pack_dup(w);
            const ulonglong2* cp = (const ulonglong2*)&cst[dl * 32];
#pragma unroll
            for (int j = 0; j < 8; j++) {
                ulonglong2 p = cp[j];
                acc[2 * j]     = ffma2(w2, p.x, acc[2 * j]);
                acc[2 * j + 1] = ffma2(w2, p.y, acc[2 * j + 1]);
            }
        }
    }
    float ob = outb[v];
#pragma unroll
    for (int j = 0; j < 16; j++) {
        float lo, hi;
        unpack2(acc[j], lo, hi);
        out[(size_t)(2 * j) * VV + v]     = lo + ob;
        out[(size_t)(2 * j + 1) * VV + v] = hi + ob;
    }
}

// ======================= launch =======================
extern "C" void kernel_launch(void* const* d_in, const int* in_sizes, int n_in,
                              void* d_out, int out_size)
{
    const int*   seq   = (const int*)d_in[0];
    const float* embed = (const float*)d_in[1];
    const float* ff1w  = (const float*)d_in[2];
    const float* ff1b  = (const float*)d_in[3];
    const float* ff2w  = (const float*)d_in[4];
    const float* ff2b  = (const float*)d_in[5];
    const float* lng   = (const float*)d_in[6];
    const float* lnb   = (const float*)d_in[7];
    const float* wgw   = (const float*)d_in[8];
    const float* wgb   = (const float*)d_in[9];
    const float* demw  = (const float*)d_in[10];
    const float* demb  = (const float*)d_in[11];
    const float* qw    = (const float*)d_in[12];
    const float* qb    = (const float*)d_in[13];
    const float* outw  = (const float*)d_in[14];
    const float* outb  = (const float*)d_in[15];
    float* out = (float*)d_out;

    float *pAhi, *pAlo, *pYhi, *pYlo, *pW1hi, *pW1lo, *pW2hi, *pW2lo;
    cudaGetSymbolAddress((void**)&pAhi, gAhi);
    cudaGetSymbolAddress((void**)&pAlo, gAlo);
    cudaGetSymbolAddress((void**)&pYhi, gYhi);
    cudaGetSymbolAddress((void**)&pYlo, gYlo);
    cudaGetSymbolAddress((void**)&pW1hi, gW1hi);
    cudaGetSymbolAddress((void**)&pW1lo, gW1lo);
    cudaGetSymbolAddress((void**)&pW2hi, gW2hi);
    cudaGetSymbolAddress((void**)&pW2lo, gW2lo);

    static bool attr_done = false;
    if (!attr_done) {
        cudaFuncSetAttribute(mma_gemm<512, true>,   cudaFuncAttributeMaxDynamicSharedMemorySize, SMEM_REQ);
        cudaFuncSetAttribute(mma_gemm<1024, false>, cudaFuncAttributeMaxDynamicSharedMemorySize, SMEM_REQ);
        attr_done = true;
    }

    // prep fragments
    prep_tok_frag<<<(MR / 16) * (512 / 8) * 32 / 256, 256>>>(seq, embed);
    prep_w_frag<<<(1024 / 8) * (512 / 8) * 32 / 256, 256>>>(ff1w, 512 / 8, 1024, pW1hi, pW1lo);
    prep_w_frag<<<(512 / 8) * (1024 / 8) * 32 / 256, 256>>>(ff2w, 1024 / 8, 512, pW2hi, pW2lo);

    // FFN GEMMs (3xTF32)
    mma_gemm<512, true><<<dim3(1024 / 128, MR / 128), 256, SMEM_REQ>>>(
        pAhi, pAlo, pW1hi, pW1lo, ff1b, seq, embed);
    mma_gemm<1024, false><<<dim3(512 / 128, MR / 128), 256, SMEM_REQ>>>(
        pYhi, pYlo, pW2hi, pW2lo, ff2b, seq, embed);

    ln_kernel<<<MR, 256>>>(lng, lnb, wgw, wgb, demw, demb);
    q_kernel<<<dim3(4, BB), 128>>>(qw, qb);
    scan_kernel<<<BB, 32>>>();
    readhead_kernel<<<BB, 128>>>();
    out_kernel<<<VV / 256, 256>>>(outw, outb, out);
}